// round 15
// baseline (speedup 1.0000x reference)
#include <cuda_runtime.h>
#include <cuda_bf16.h>

#define BB 16
#define TT 800
#define VV 4000
#define LL 100
#define SS 201        // 2L+1 states
#define EW 208        // emission row stride (floats): 832B rows
#define BUF 1728      // shared buffer floats: 8*EW + 64 pad
#define NEGV (-1e30f)
#define LAMB 0.1f
#define LN2D 0.6931471805599453094
#define ADOPT_BLKS 14 // full renorm (zero-lane adoption) for first 14 blocks

// Scratch (__device__ globals per allocation-free rule)
__device__ float g_lse[BB * TT];
__device__ float g_m2[BB * TT];
__device__ __align__(16) float g_em[(size_t)BB * TT * EW];  // 10.6 MB
__device__ float g_cost[BB];
__device__ int g_cnt;  // arrival counter (self-resetting -> graph-replay safe)

typedef unsigned long long u64t;

// ---- packed f32x2 primitives (FFMA2 path: only reachable via PTX) ----
__device__ __forceinline__ u64t pk2(float lo, float hi) {
    u64t r; asm("mov.b64 %0, {%1, %2};" : "=l"(r) : "f"(lo), "f"(hi)); return r;
}
__device__ __forceinline__ void upk2(u64t p, float& lo, float& hi) {
    asm("mov.b64 {%0, %1}, %2;" : "=f"(lo), "=f"(hi) : "l"(p));
}
__device__ __forceinline__ u64t fma2(u64t a, u64t b, u64t c) {
    u64t r; asm("fma.rn.f32x2 %0, %1, %2, %3;" : "=l"(r) : "l"(a), "l"(b), "l"(c));
    return r;
}
__device__ __forceinline__ u64t mul2(u64t a, u64t b) {
    u64t r; asm("mul.rn.f32x2 %0, %1, %2;" : "=l"(r) : "l"(a), "l"(b)); return r;
}
__device__ __forceinline__ u64t add2(u64t a, u64t b) {
    u64t r; asm("add.rn.f32x2 %0, %1, %2;" : "=l"(r) : "l"(a), "l"(b)); return r;
}

__inline__ __device__ float warp_max(float v) {
#pragma unroll
    for (int o = 16; o; o >>= 1) v = fmaxf(v, __shfl_xor_sync(0xffffffffu, v, o));
    return v;
}
__inline__ __device__ float warp_sum(float v) {
#pragma unroll
    for (int o = 16; o; o >>= 1) v += __shfl_xor_sync(0xffffffffu, v, o);
    return v;
}
__device__ __forceinline__ unsigned smem_u32(const void* p) {
    return (unsigned)__cvta_generic_to_shared(p);
}
__device__ __forceinline__ void cp_async16(unsigned dst, const void* src) {
    asm volatile("cp.async.cg.shared.global [%0], [%1], 16;" :: "r"(dst), "l"(src) : "memory");
}

// ============================================================================
// Kernel 1: per-(b,t) single-pass sum-of-exp lse + gather of the 201
// extended-state logits -> max-normalized LINEAR fp32 emissions.
// Rows with t >= input_lengths[b] are skipped entirely.
// ============================================================================
__global__ __launch_bounds__(256) void lse_gather_kernel(
    const float* __restrict__ logits, const int* __restrict__ labels,
    const int* __restrict__ input_lengths) {
    const int t = blockIdx.x, b = blockIdx.y;
    if (t >= __ldg(input_lengths + b)) return;

    const int bt = b * TT + t;
    const float* __restrict__ row = logits + (size_t)bt * VV;
    const int tid = threadIdx.x;
    const int lane = tid & 31, wid = tid >> 5;

    float s = 0.0f;
#pragma unroll
    for (int i = 0; i < 4; i++) {
        int idx = tid + i * 256;
        if (idx < VV / 4) {
            float4 v = reinterpret_cast<const float4*>(row)[idx];
            s += __expf(v.x) + __expf(v.y) + __expf(v.z) + __expf(v.w);
        }
    }
    __shared__ float ssum[8], sgm[8];
    s = warp_sum(s);
    if (lane == 0) ssum[wid] = s;

    float val = NEGV;
    if (tid <= 200) {
        int vv = (tid & 1) ? labels[b * LL + (tid >> 1)] : 0;
        val = __ldg(row + vv);
    }
    float gm = warp_max(val);
    if (lane == 0) sgm[wid] = gm;
    __syncthreads();

    s = ssum[0];
    gm = sgm[0];
#pragma unroll
    for (int i = 1; i < 8; i++) { s += ssum[i]; gm = fmaxf(gm, sgm[i]); }
    const float lse = __logf(s);

    if (tid < EW)
        g_em[(size_t)bt * EW + tid] = (tid <= 200) ? __expf(val - gm) : 0.0f;
    if (tid == 0) {
        g_lse[bt] = lse;
        g_m2[bt] = gm - lse;
    }
}

// ============================================================================
// Kernel 2: bidirectional CTC DP with PACKED f32x2 state updates — halves the
// fma-pipe instruction stream of the issue-bound serial loop.
//   warp 0: forward alpha t=0..c  (c=(len-1)/2)
//   warp 1: backward beta t=len-1..c+1
//   warp 2: costs_den = sum lse, corr = sum m2
// ============================================================================
// Forward step. Pairs P_k=(v[2k],v[2k+1]); S_k=(v[2k-1],v[2k]); D_k has
// v[2k-1] in its HIGH half (D_k = P_{k-1} for k>0); M_k=(0,m_{2k+1}).
// U=fma2(M,D,S) -> W=mul2(U,E) -> P=fma2(P,E,W): bit-identical to scalar form.
__device__ __forceinline__ void dpstep2(float v[8], u64t ea, u64t eb, u64t ec,
                                        u64t ed, int lane, u64t M0, u64t M1,
                                        u64t M2, u64t M3, float fD) {
    float hi1 = __shfl_up_sync(0xffffffffu, v[7], 1);
    const float hiX = (lane == 0) ? 0.0f : hi1 * fD;
    const u64t P0 = pk2(v[0], v[1]), P1 = pk2(v[2], v[3]);
    const u64t P2 = pk2(v[4], v[5]), P3 = pk2(v[6], v[7]);
    const u64t S0 = pk2(hiX, v[0]), S1 = pk2(v[1], v[2]);
    const u64t S2 = pk2(v[3], v[4]), S3 = pk2(v[5], v[6]);
    const u64t D0 = pk2(0.0f, hiX);
    const u64t U0 = fma2(M0, D0, S0);
    const u64t U1 = fma2(M1, P0, S1);
    const u64t U2 = fma2(M2, P1, S2);
    const u64t U3 = fma2(M3, P2, S3);
    const u64t R0 = fma2(P0, ea, mul2(U0, ea));
    const u64t R1 = fma2(P1, eb, mul2(U1, eb));
    const u64t R2 = fma2(P2, ec, mul2(U2, ec));
    const u64t R3 = fma2(P3, ed, mul2(U3, ed));
    upk2(R0, v[0], v[1]); upk2(R1, v[2], v[3]);
    upk2(R2, v[4], v[5]); upk2(R3, v[6], v[7]);
}

// Backward step. W_k=(w[2k],w[2k+1]) with w=b*e; S_k=(w[2k+1],w[2k+2]);
// skip source for odd j is hi(W_{k+1}); boundary halo from right lane.
__device__ __forceinline__ void bstep2(float b[8], u64t ea, u64t eb, u64t ec,
                                       u64t ed, int lane, u64t A0, u64t A1,
                                       u64t A2, u64t A3, float fD) {
    const u64t B0 = pk2(b[0], b[1]), B1 = pk2(b[2], b[3]);
    const u64t B2 = pk2(b[4], b[5]), B3 = pk2(b[6], b[7]);
    const u64t W0 = mul2(B0, ea), W1 = mul2(B1, eb);
    const u64t W2 = mul2(B2, ec), W3 = mul2(B3, ed);
    float w0, w1, w2, w3, w4, w5, w6, w7;
    upk2(W0, w0, w1); upk2(W1, w2, w3); upk2(W2, w4, w5); upk2(W3, w6, w7);
    float h0 = __shfl_down_sync(0xffffffffu, w0, 1);
    float h1 = __shfl_down_sync(0xffffffffu, w1, 1);
    if (lane == 31) { h0 = 0.0f; h1 = 0.0f; }
    h0 *= fD; h1 *= fD;
    const u64t S0 = pk2(w1, w2), S1 = pk2(w3, w4);
    const u64t S2 = pk2(w5, w6), S3 = pk2(w7, h0);
    const u64t D3 = pk2(0.0f, h1);
    const u64t R0 = add2(W0, fma2(A0, W1, S0));
    const u64t R1 = add2(W1, fma2(A1, W2, S1));
    const u64t R2 = add2(W2, fma2(A2, W3, S2));
    const u64t R3 = add2(W3, fma2(A3, D3, S3));
    upk2(R0, b[0], b[1]); upk2(R1, b[2], b[3]);
    upk2(R2, b[4], b[5]); upk2(R3, b[6], b[7]);
}

__device__ __forceinline__ int renorm_local(float v[8]) {
    float m = 0.0f;
#pragma unroll
    for (int j = 0; j < 8; j++) m = fmaxf(m, v[j]);
    if (m == 0.0f) return 0x40000000;
    const int e = ((__float_as_int(m) >> 23) & 255) - 127;
    const float f = __int_as_float((unsigned)(127 - e) << 23);
#pragma unroll
    for (int j = 0; j < 8; j++) v[j] *= f;
    return e;
}
__device__ __forceinline__ void renormF(float v[8], int& ex, int lane, float& fD) {
    const int e = renorm_local(v);
    int zi = (e == 0x40000000) ? 1 : 0;
    if (!zi) ex += e;
#pragma unroll
    for (int d = 1; d <= 4; d <<= 1) {
        const int exu = __shfl_up_sync(0xffffffffu, ex, d);
        const int zu = __shfl_up_sync(0xffffffffu, zi, d);
        if (lane >= d && zi) { ex = exu; zi = zu; }
    }
    const int exl = __shfl_up_sync(0xffffffffu, ex, 1);
    int dlt = (lane == 0) ? 0 : (exl - ex);
    dlt = max(-126, min(112, dlt));
    fD = __int_as_float((unsigned)(dlt + 127) << 23);
}
__device__ __forceinline__ void renormFc(float v[8], int& ex, int lane, float& fD) {
    const int e = renorm_local(v);
    if (e != 0x40000000) ex += e;
    const int exl = __shfl_up_sync(0xffffffffu, ex, 1);
    int dlt = (lane == 0) ? 0 : (exl - ex);
    dlt = max(-126, min(112, dlt));
    fD = __int_as_float((unsigned)(dlt + 127) << 23);
}
__device__ __forceinline__ void renormB(float v[8], int& ex, int lane, float& fD) {
    const int e = renorm_local(v);
    int zi = (e == 0x40000000) ? 1 : 0;
    if (!zi) ex += e;
#pragma unroll
    for (int d = 1; d <= 4; d <<= 1) {
        const int exd = __shfl_down_sync(0xffffffffu, ex, d);
        const int zd = __shfl_down_sync(0xffffffffu, zi, d);
        if (lane < 32 - d && zi) { ex = exd; zi = zd; }
    }
    const int exr = __shfl_down_sync(0xffffffffu, ex, 1);
    int dlt = (lane == 31) ? 0 : (exr - ex);
    dlt = max(-126, min(112, dlt));
    fD = __int_as_float((unsigned)(dlt + 127) << 23);
}
__device__ __forceinline__ void renormBc(float v[8], int& ex, int lane, float& fD) {
    const int e = renorm_local(v);
    if (e != 0x40000000) ex += e;
    const int exr = __shfl_down_sync(0xffffffffu, ex, 1);
    int dlt = (lane == 31) ? 0 : (exr - ex);
    dlt = max(-126, min(112, dlt));
    fD = __int_as_float((unsigned)(dlt + 127) << 23);
}

__global__ __launch_bounds__(96) void ctc_dp_kernel(
    const int* __restrict__ labels,
    const int* __restrict__ input_lengths,
    const int* __restrict__ label_lengths,
    float* __restrict__ out) {
    const int b = blockIdx.x;
    const int tid = threadIdx.x;
    const int lane = tid & 31, w = tid >> 5;

    __shared__ __align__(16) float eshf[2][BUF];
    __shared__ __align__(16) float eshb[2][BUF];
    __shared__ float sB[256];
    __shared__ int sExB[32];
    __shared__ float s_den, s_corr, s_tot;
    __shared__ int s_ex;

    const int len = input_lengths[b];
    const int c = (len - 1) >> 1;            // forward covers 0..c
    const char* gbase = (const char*)(g_em + (size_t)b * TT * EW);

    float vF[8];
    int exF = 0;

    if (w == 2) {
        float d = 0.0f, cc = 0.0f;
        for (int t = lane; t < len; t += 32) {
            d += g_lse[b * TT + t];
            cc += g_m2[b * TT + t];
        }
        d = warp_sum(d);
        cc = warp_sum(cc);
        if (lane == 0) { s_den = d; s_corr = cc; }
    } else if (w == 0) {
        // ---------------- forward warp ----------------
        eshf[0][8 * EW + lane] = 0.0f; eshf[0][8 * EW + 32 + lane] = 0.0f;
        eshf[1][8 * EW + lane] = 0.0f; eshf[1][8 * EW + 32 + lane] = 0.0f;
        __syncwarp();

        const int s0 = lane * 8;
        u64t M0, M1, M2, M3;
        {
            const int* lb = labels + b * LL;
            float mm[4];
#pragma unroll
            for (int j = 1; j < 8; j += 2) {
                int s = s0 + j;
                float a = 0.0f;
                if (s >= 3 && s <= 200) {
                    int i = s >> 1;
                    a = (lb[i] != lb[i - 1]) ? 1.0f : 0.0f;
                }
                mm[j >> 1] = a;
            }
            M0 = pk2(0.0f, mm[0]); M1 = pk2(0.0f, mm[1]);
            M2 = pk2(0.0f, mm[2]); M3 = pk2(0.0f, mm[3]);
        }

        const unsigned ebase = smem_u32(&eshf[0][0]);
        const int rf = c + 1;                 // rows 0..c
        const int nbf = (rf + 7) >> 3;

#define ISSUE_F(ib) do {                                                         \
        if ((ib) < nbf) {                                                        \
            const char* _s = gbase + (size_t)(ib) * 6656 + lane * 16;            \
            unsigned _d = ebase + (((ib) & 1) * (BUF * 4)) + lane * 16;          \
            _Pragma("unroll")                                                    \
            for (int _k = 0; _k < 13; _k++) cp_async16(_d + _k * 512, _s + _k * 512); \
        }                                                                        \
        asm volatile("cp.async.commit_group;" ::: "memory");                     \
    } while (0)

        ISSUE_F(0);
        ISSUE_F(1);

#pragma unroll
        for (int j = 0; j < 8; j++) vF[j] = 0.0f;
        float fD = 1.0f;

        for (int ib = 0; ib < nbf; ib++) {
            asm volatile("cp.async.wait_group 1;" ::: "memory");
            const float* base = &eshf[ib & 1][0];
            const float* lp = base + lane * 8;
            const int lim = min(8, rf - ib * 8);
            if (ib == 0) {
                if (lane == 0) { vF[0] = base[0]; vF[1] = base[1]; }
                ulonglong2 ca = *(const ulonglong2*)(lp + EW);
                ulonglong2 cb = *(const ulonglong2*)(lp + EW + 4);
#pragma unroll
                for (int tt = 1; tt < 8; tt++) {
                    ulonglong2 na = ca, nb = cb;
                    if (tt < 7) {
                        na = *(const ulonglong2*)(lp + (tt + 1) * EW);
                        nb = *(const ulonglong2*)(lp + (tt + 1) * EW + 4);
                    }
                    dpstep2(vF, ca.x, ca.y, cb.x, cb.y, lane, M0, M1, M2, M3, fD);
                    ca = na; cb = nb;
                }
            } else if (lim == 8) {
                ulonglong2 ca = *(const ulonglong2*)(lp);
                ulonglong2 cb = *(const ulonglong2*)(lp + 4);
#pragma unroll
                for (int tt = 0; tt < 8; tt++) {
                    ulonglong2 na = ca, nb = cb;
                    if (tt < 7) {
                        na = *(const ulonglong2*)(lp + (tt + 1) * EW);
                        nb = *(const ulonglong2*)(lp + (tt + 1) * EW + 4);
                    }
                    dpstep2(vF, ca.x, ca.y, cb.x, cb.y, lane, M0, M1, M2, M3, fD);
                    ca = na; cb = nb;
                }
            } else {
                for (int tt = 0; tt < lim; tt++) {
                    ulonglong2 ea = *(const ulonglong2*)(lp + tt * EW);
                    ulonglong2 eb = *(const ulonglong2*)(lp + tt * EW + 4);
                    dpstep2(vF, ea.x, ea.y, eb.x, eb.y, lane, M0, M1, M2, M3, fD);
                }
            }
            if (ib < ADOPT_BLKS) renormF(vF, exF, lane, fD);
            else renormFc(vF, exF, lane, fD);
            ISSUE_F(ib + 2);
        }
    } else {
        // ---------------- backward warp ----------------
        eshb[0][8 * EW + lane] = 0.0f; eshb[0][8 * EW + 32 + lane] = 0.0f;
        eshb[1][8 * EW + lane] = 0.0f; eshb[1][8 * EW + 32 + lane] = 0.0f;
        __syncwarp();

        const int s0 = lane * 8;
        u64t A0, A1, A2, A3;
        {
            const int* lb = labels + b * LL;
            float aa[4];
#pragma unroll
            for (int j = 1; j < 8; j += 2) {
                int sp = s0 + j + 2;
                float a = 0.0f;
                if (sp <= 200) {
                    int i = sp >> 1;
                    a = (lb[i] != lb[i - 1]) ? 1.0f : 0.0f;
                }
                aa[j >> 1] = a;
            }
            A0 = pk2(0.0f, aa[0]); A1 = pk2(0.0f, aa[1]);
            A2 = pk2(0.0f, aa[2]); A3 = pk2(0.0f, aa[3]);
        }

        const unsigned ebase = smem_u32(&eshb[0][0]);
        const int rb = len - 1 - c;               // rows len-1 .. c+1
        const int nbb = (rb + 7) >> 3;

        // block k stages rows [len-8-8k .. len-1-8k]; consumed descending
#define ISSUE_B(k) do {                                                          \
        if ((k) < nbb) {                                                         \
            const char* _s = gbase + (size_t)(len - 8 - 8 * (k)) * 832 + lane * 16; \
            unsigned _d = ebase + (((k) & 1) * (BUF * 4)) + lane * 16;           \
            _Pragma("unroll")                                                    \
            for (int _k = 0; _k < 13; _k++) cp_async16(_d + _k * 512, _s + _k * 512); \
        }                                                                        \
        asm volatile("cp.async.commit_group;" ::: "memory");                     \
    } while (0)

        ISSUE_B(0);
        ISSUE_B(1);

        const int end = 2 * label_lengths[b];
        float vB[8];
#pragma unroll
        for (int j = 0; j < 8; j++) {
            int s = s0 + j;
            vB[j] = (s == end || s == end - 1) ? 1.0f : 0.0f;
        }
        int exB = 0;
        float fD = 1.0f;

        for (int k = 0; k < nbb; k++) {
            asm volatile("cp.async.wait_group 1;" ::: "memory");
            const float* base = &eshb[k & 1][0];
            const float* lp = base + lane * 8;
            const int hi = len - 1 - 8 * k;
            const int lim = min(8, hi - c);       // consume rows hi..hi-lim+1
            if (lim == 8) {
                ulonglong2 ca = *(const ulonglong2*)(lp + 7 * EW);
                ulonglong2 cb = *(const ulonglong2*)(lp + 7 * EW + 4);
#pragma unroll
                for (int tt = 0; tt < 8; tt++) {
                    ulonglong2 na = ca, nb = cb;
                    if (tt < 7) {
                        na = *(const ulonglong2*)(lp + (6 - tt) * EW);
                        nb = *(const ulonglong2*)(lp + (6 - tt) * EW + 4);
                    }
                    bstep2(vB, ca.x, ca.y, cb.x, cb.y, lane, A0, A1, A2, A3, fD);
                    ca = na; cb = nb;
                }
            } else {
                for (int tt = 0; tt < lim; tt++) {
                    ulonglong2 ea = *(const ulonglong2*)(lp + (7 - tt) * EW);
                    ulonglong2 eb = *(const ulonglong2*)(lp + (7 - tt) * EW + 4);
                    bstep2(vB, ea.x, ea.y, eb.x, eb.y, lane, A0, A1, A2, A3, fD);
                }
            }
            if (k < ADOPT_BLKS) renormB(vB, exB, lane, fD);
            else renormBc(vB, exB, lane, fD);
            ISSUE_B(k + 2);
        }

        // publish beta_c frames
#pragma unroll
        for (int j = 0; j < 8; j++) sB[s0 + j] = vB[j];
        sExB[lane] = exB;
    }
    __syncthreads();

    if (w == 0) {
        // Total = sum_s alpha_c[s] * beta_c[s]
        float p = 0.0f;
        const int s0 = lane * 8;
#pragma unroll
        for (int j = 0; j < 8; j++) p += vF[j] * sB[s0 + j];
        const int e = exF + sExB[lane];
        int exv = (p > 0.0f) ? e : (int)0xC0000000;
        int exm = exv;
#pragma unroll
        for (int o = 16; o; o >>= 1) exm = max(exm, __shfl_xor_sync(0xffffffffu, exm, o));
        float a = (p > 0.0f) ? p * exp2f((float)(e - exm)) : 0.0f;
        a = warp_sum(a);
        if (lane == 0) { s_tot = a; s_ex = exm; }
    }
    __syncthreads();
    if (tid == 0) {
        const double lognum = log((double)s_tot) + (double)s_ex * LN2D + (double)s_corr;
        const float nll = -(float)lognum;
        g_cost[b] = s_den - (1.0f + LAMB) * nll;

        // ---- fused finalize: last CTA to arrive computes the mean ----
        __threadfence();
        const int arrived = atomicAdd(&g_cnt, 1);
        if (arrived == BB - 1) {
            float s = 0.0f;
#pragma unroll
            for (int i = 0; i < BB; i++) s += g_cost[i];
            out[0] = s / (float)BB;
            g_cnt = 0;  // reset for next graph replay
        }
    }
}

extern "C" void kernel_launch(void* const* d_in, const int* in_sizes, int n_in,
                              void* d_out, int out_size) {
    const float* logits = (const float*)d_in[0];
    const int* labels = (const int*)d_in[1];
    const int* input_lengths = (const int*)d_in[2];
    const int* label_lengths = (const int*)d_in[3];
    float* out = (float*)d_out;

    dim3 g1(TT, BB);
    lse_gather_kernel<<<g1, 256>>>(logits, labels, input_lengths);
    ctc_dp_kernel<<<BB, 96>>>(labels, input_lengths, label_lengths, out);
}